// round 15
// baseline (speedup 1.0000x reference)
#include <cuda_runtime.h>
#include <cuda_fp16.h>
#include <cstdint>
#include <math.h>

#define NROWS 131072
#define DDIM  64
#define KCB   512
#define TILE_M 128
#define NTILES (NROWS / TILE_M)     // 1024
#define GRID_MAIN 148
#define THREADS 512
#define CAP 2048                    // per-code bucket capacity (mean 256)

#define OFF_Q    0
#define OFF_LOSS (NROWS * DDIM)
#define OFF_PERP (OFF_LOSS + 1)
#define OFF_EMB  (OFF_PERP + 1)
#define OFF_IDX  (OFF_EMB + DDIM * KCB)

#define MARGIN 0.15625f
#define MASKH  0xFFFFFE00u
#define KEYBIAS 256.0f
#define SENT 0x7F7FFFFFu

__device__ float g_dw[DDIM * KCB];
__device__ float g_cluster[KCB];
__device__ float g_loss;
__device__ float g_enorm[KCB];
__device__ __align__(16) float g_ecbT[KCB * DDIM];   // codebook transposed [k][d]
__device__ int   g_cnt[KCB];        // per-code scatter counters
__device__ int   g_perm[KCB * CAP]; // per-code row buckets
__device__ uint2 g_que[NROWS];
__device__ int   g_que2[NROWS];
__device__ int   g_qn, g_qn2;

__device__ __forceinline__ uint32_t pb(uint32_t d) {
    return ((d >> 1) & 3u) * 32u + (d >> 4) * 8u + ((d >> 3) & 1u) * 4u + (d & 1u) * 2u;
}

// smem layout (bytes) for k_main
#define SO_EH    0u          // 65536
#define SO_XH    65536u      // 16384
#define SO_EN2   81920u      // 2048
#define SO_XN    83968u      // 1024 (2x512 double-buffered)
#define SO_TOP   84992u      // 8192 (2x4096 double-buffered)
#define SO_HIST  93184u      // 2048
#define SMEM_SZ  95232u

__device__ __forceinline__ void mma_f16(float* d, uint32_t a0, uint32_t a1,
                                        uint32_t a2, uint32_t a3,
                                        uint32_t b0, uint32_t b1) {
    asm volatile(
        "mma.sync.aligned.m16n8k16.row.col.f32.f16.f16.f32 "
        "{%0,%1,%2,%3}, {%4,%5,%6,%7}, {%8,%9}, {%0,%1,%2,%3};\n"
        : "+f"(d[0]), "+f"(d[1]), "+f"(d[2]), "+f"(d[3])
        : "r"(a0), "r"(a1), "r"(a2), "r"(a3), "r"(b0), "r"(b1));
}

__device__ __forceinline__ void ins3(uint32_t& m1, uint32_t& m2, uint32_t& m3,
                                     uint32_t k) {
    uint32_t h1 = max(m1, k); m1 = min(m1, k);
    uint32_t h2 = max(m2, h1); m2 = min(m2, h1);
    m3 = min(m3, h2);
}
__device__ __forceinline__ uint32_t mkkey(float dist, uint32_t n) {
    uint32_t r;
    asm("bfi.b32 %0, %1, %2, 0, 9;" : "=r"(r) : "r"(n), "r"(__float_as_uint(dist)));
    return r;
}

// scatter a row into its code bucket; overflow falls back to direct atomics
__device__ __forceinline__ void scatter_row(int bidx, int row,
                                            const float* __restrict__ x) {
    int pos = atomicAdd(&g_cnt[bidx], 1);
    if (pos < CAP) {
        g_perm[bidx * CAP + pos] = row;
    } else {
        const float* xr = x + (size_t)row * DDIM;
        for (int d = 0; d < DDIM; d++)
            atomicAdd(&g_dw[d * KCB + bidx], xr[d]);
    }
}

__device__ __forceinline__ void do_kb(
    const char* sm, int kb, int g, int q,
    const uint4& A0a, const uint4& A0b, const uint4& A1a, const uint4& A1b,
    const float* s_en2, uint32_t c0, uint32_t c1,
    uint32_t& m11, uint32_t& m12, uint32_t& m13,
    uint32_t& m21, uint32_t& m22, uint32_t& m23)
{
    float acc[8][4];
#pragma unroll
    for (int nt = 0; nt < 8; nt++)
#pragma unroll
        for (int j = 0; j < 4; j++) acc[nt][j] = 0.f;

#pragma unroll
    for (int nt = 0; nt < 8; nt++) {
        uint32_t rowb = (uint32_t)(kb * 64 + nt * 8 + g) * 128u;
        uint4 B0 = *(const uint4*)(sm + SO_EH + rowb + c0);
        uint4 B1 = *(const uint4*)(sm + SO_EH + rowb + c1);
        mma_f16(acc[nt], A0a.x, A1a.x, A0a.y, A1a.y, B0.x, B0.y);
        mma_f16(acc[nt], A0a.z, A1a.z, A0a.w, A1a.w, B0.z, B0.w);
        mma_f16(acc[nt], A0b.x, A1b.x, A0b.y, A1b.y, B1.x, B1.y);
        mma_f16(acc[nt], A0b.z, A1b.z, A0b.w, A1b.w, B1.z, B1.w);
    }
#pragma unroll
    for (int nt = 0; nt < 8; nt++) {
        uint32_t n0 = (uint32_t)(kb * 64 + nt * 8 + q * 2);
        float2 en = *(const float2*)&s_en2[n0];
        uint32_t k0 = mkkey(fmaf(-2.f, acc[nt][0], en.x), n0);
        uint32_t k1 = mkkey(fmaf(-2.f, acc[nt][1], en.y), n0 + 1);
        uint32_t k2 = mkkey(fmaf(-2.f, acc[nt][2], en.x), n0);
        uint32_t k3 = mkkey(fmaf(-2.f, acc[nt][3], en.y), n0 + 1);
        ins3(m11, m12, m13, k0);
        ins3(m11, m12, m13, k1);
        ins3(m21, m22, m23, k2);
        ins3(m21, m22, m23, k3);
    }
}

// ---------------------------------------------------------------------------
// Prep (grid 64 x 512): enorm, transposed codebook, zero dw/cnt, reset queues
// ---------------------------------------------------------------------------
__global__ void k_prep(const float* __restrict__ emb) {
    __shared__ float red[8][64];
    const int t = threadIdx.x, b = blockIdx.x;

    g_dw[b * 512 + t] = 0.f;
    {
        int k = b * 8 + (t >> 6), d = t & 63;
        g_ecbT[k * 64 + d] = emb[d * KCB + k];
    }
    if (b < 8) {
        const int kk = t & 63, part = t >> 6;
        const int k = b * 64 + kk;
        float s = 0.f;
#pragma unroll
        for (int j = 0; j < 8; j++) {
            float e = emb[(part * 8 + j) * KCB + k];
            s = fmaf(e, e, s);
        }
        red[part][kk] = s;
        __syncthreads();
        if (t < 64) {
            float tot = red[0][t];
#pragma unroll
            for (int p = 1; p < 8; p++) tot += red[p][t];
            g_enorm[b * 64 + t] = tot;
        }
    }
    if (b == 62) g_cnt[t] = 0;
    if (b == 63) {
        g_cluster[t] = 0.f;
        if (t == 0) { g_loss = 0.f; g_qn = 0; g_qn2 = 0; }
    }
}

// ---------------------------------------------------------------------------
// Main: 512 threads; K-split halves; 2 barriers/tile; scatter on emit
// ---------------------------------------------------------------------------
__global__ __launch_bounds__(THREADS, 1)
void k_main(const float* __restrict__ x, const float* __restrict__ emb,
            float* __restrict__ out_q, float* __restrict__ out_idx) {
    extern __shared__ __align__(1024) char sm[];
    const int tid  = threadIdx.x;
    const int wid  = tid >> 5;
    const int lane = tid & 31;
    const int g    = lane >> 2;
    const int q    = lane & 3;
    const int half = wid >> 3;
    const int w8   = wid & 7;

    float* s_en2  = (float*)(sm + SO_EN2);
    float* s_xn   = (float*)(sm + SO_XN);
    uint4* s_top  = (uint4*)(sm + SO_TOP);
    int*   s_hist = (int*)(sm + SO_HIST);

    for (int i = tid; i < DDIM * KCB; i += THREADS) {
        uint32_t d = (uint32_t)i >> 9, k = (uint32_t)i & 511u;
        uint32_t off = k * 128u + (pb(d) ^ ((k & 7u) * 16u));
        *(__half*)(sm + SO_EH + off) = __float2half_rn(emb[i]);
    }
    s_en2[tid] = g_enorm[tid] + KEYBIAS;
    s_hist[tid] = 0;
    __syncthreads();

    const int r0 = w8 * 16 + g;
    const int r1 = r0 + 8;
    const uint32_t c0 = ((uint32_t)q * 32u) ^ ((uint32_t)g * 16u);
    const uint32_t c1 = ((uint32_t)q * 32u + 16u) ^ ((uint32_t)g * 16u);

    float loss_acc = 0.f;
    int buf = 0;

    for (int tile = blockIdx.x; tile < NTILES; tile += gridDim.x) {
        const float* xt = x + (size_t)tile * TILE_M * DDIM;

#pragma unroll
        for (int it = 0; it < 4; it++) {
            int i = it * THREADS + tid;
            float4 v = ((const float4*)xt)[i];
            uint32_t r = (uint32_t)i >> 4, c = ((uint32_t)i & 15u) * 4u;
            uint32_t xw = (r & 7u) * 16u;
            *(__half2*)(sm + SO_XH + r * 128u + (pb(c) ^ xw)) =
                __floats2half2_rn(v.x, v.y);
            *(__half2*)(sm + SO_XH + r * 128u + (pb(c + 2) ^ xw)) =
                __floats2half2_rn(v.z, v.w);
            float pn = fmaf(v.x, v.x, fmaf(v.y, v.y, fmaf(v.z, v.z, v.w * v.w)));
            pn += __shfl_xor_sync(0xffffffffu, pn, 1);
            pn += __shfl_xor_sync(0xffffffffu, pn, 2);
            pn += __shfl_xor_sync(0xffffffffu, pn, 4);
            pn += __shfl_xor_sync(0xffffffffu, pn, 8);
            if ((tid & 15) == 0) s_xn[buf * 128 + r] = pn;
        }
        __syncthreads();   // barrier 1

        uint4 A0a = *(const uint4*)(sm + SO_XH + (uint32_t)r0 * 128u + c0);
        uint4 A0b = *(const uint4*)(sm + SO_XH + (uint32_t)r0 * 128u + c1);
        uint4 A1a = *(const uint4*)(sm + SO_XH + (uint32_t)r1 * 128u + c0);
        uint4 A1b = *(const uint4*)(sm + SO_XH + (uint32_t)r1 * 128u + c1);

        uint32_t e11 = SENT, e12 = SENT, e13 = SENT;
        uint32_t o11 = SENT, o12 = SENT, o13 = SENT;
        uint32_t e21 = SENT, e22 = SENT, e23 = SENT;
        uint32_t o21 = SENT, o22 = SENT, o23 = SENT;

#pragma unroll 1
        for (int kbp = 0; kbp < 2; kbp++) {
            do_kb(sm, half * 4 + 2 * kbp,     g, q, A0a, A0b, A1a, A1b,
                  s_en2, c0, c1, e11, e12, e13, e21, e22, e23);
            do_kb(sm, half * 4 + 2 * kbp + 1, g, q, A0a, A0b, A1a, A1b,
                  s_en2, c0, c1, o11, o12, o13, o21, o22, o23);
        }
        ins3(e11, e12, e13, o11); ins3(e11, e12, e13, o12); ins3(e11, e12, e13, o13);
        ins3(e21, e22, e23, o21); ins3(e21, e22, e23, o22); ins3(e21, e22, e23, o23);

#pragma unroll
        for (int o = 1; o <= 2; o <<= 1) {
            uint32_t q1 = __shfl_xor_sync(0xffffffffu, e11, o);
            uint32_t q2 = __shfl_xor_sync(0xffffffffu, e12, o);
            uint32_t q3 = __shfl_xor_sync(0xffffffffu, e13, o);
            ins3(e11, e12, e13, q1);
            ins3(e11, e12, e13, q2);
            ins3(e11, e12, e13, q3);
            q1 = __shfl_xor_sync(0xffffffffu, e21, o);
            q2 = __shfl_xor_sync(0xffffffffu, e22, o);
            q3 = __shfl_xor_sync(0xffffffffu, e23, o);
            ins3(e21, e22, e23, q1);
            ins3(e21, e22, e23, q2);
            ins3(e21, e22, e23, q3);
        }
        if (q == 0) {
            s_top[buf * 256 + ((r0 << 1) | half)] = make_uint4(e11, e12, e13, 0u);
            s_top[buf * 256 + ((r1 << 1) | half)] = make_uint4(e21, e22, e23, 0u);
        }
        __syncthreads();   // barrier 2

        // ---- Phase A ----
        {
            const int rloc = tid >> 2;
            const int q4   = tid & 3;
            const int row  = tile * TILE_M + rloc;
            uint4 Ka = s_top[buf * 256 + (rloc << 1)];
            uint4 Kb = s_top[buf * 256 + ((rloc << 1) | 1)];
            uint32_t m1 = Ka.x, m2 = Ka.y, m3 = Ka.z;
            ins3(m1, m2, m3, Kb.x);
            ins3(m1, m2, m3, Kb.y);
            ins3(m1, m2, m3, Kb.z);
            float d1 = __uint_as_float(m1 & MASKH);
            float d2 = __uint_as_float(m2 & MASKH);
            float d3 = __uint_as_float(m3 & MASKH);
            int bidx = (int)(m1 & 511u);
            if (d2 - d1 >= MARGIN) {
                if (q4 == 0) {
                    out_idx[row] = (float)bidx;
                    atomicAdd(&s_hist[bidx], 1);
                    scatter_row(bidx, row, x);
                    loss_acc += d1 - KEYBIAS + s_xn[buf * 128 + rloc]
                              + __uint_as_float(m1 & 0xFF800000u) * 3.0517578125e-05f;
                }
                const float4* ec = (const float4*)(g_ecbT + bidx * DDIM) + q4 * 4;
                float4* oq = (float4*)(out_q + (size_t)row * DDIM) + q4 * 4;
#pragma unroll
                for (int j = 0; j < 4; j++) oq[j] = __ldg(ec + j);
            } else if (q4 == 0) {
                if (d3 - d1 >= MARGIN) {
                    int p = atomicAdd(&g_qn, 1);
                    g_que[p] = make_uint2((unsigned)row,
                                          (m1 & 511u) | ((m2 & 511u) << 16));
                } else {
                    int p = atomicAdd(&g_qn2, 1);
                    g_que2[p] = row;
                }
            }
        }
        buf ^= 1;
    }

#pragma unroll
    for (int o = 16; o > 0; o >>= 1)
        loss_acc += __shfl_xor_sync(0xffffffffu, loss_acc, o);
    if (lane == 0) atomicAdd(&g_loss, loss_acc);

    __syncthreads();
    {
        int c = s_hist[tid];
        if (c) atomicAdd(&g_cluster[tid], (float)c);
    }
}

// ---------------------------------------------------------------------------
// Fix: exact fp32 resolution of queued rows (+ scatter)
// ---------------------------------------------------------------------------
#define FX_XROW (64 * 513)
#define FX_B64  (64 * 513 + 64)
#define FX_SZ   ((64 * 513 + 66) * 4)

__global__ __launch_bounds__(512)
void k_fix(const float* __restrict__ x, const float* __restrict__ emb,
           float* __restrict__ out_q, float* __restrict__ out_idx) {
    extern __shared__ float se[];
    const int tid = threadIdx.x;
    const int wid = tid >> 5;
    const int lane = tid & 31;
    float* xrow = se + FX_XROW;
    unsigned long long* b64 = (unsigned long long*)(se + FX_B64);

    for (int i = tid; i < 64 * 512; i += 512) {
        int d = i >> 9, k = i & 511;
        se[d * 513 + k] = emb[i];
    }
    __syncthreads();

    float loss_acc = 0.f;

    const int qn = g_qn;
    for (int j = blockIdx.x * 16 + wid; j < qn; j += gridDim.x * 16) {
        uint2 e = g_que[j];
        const int row = (int)e.x;
        const int i1 = (int)(e.y & 511u), i2 = (int)((e.y >> 16) & 511u);
        float2 xv = __ldg((const float2*)(x + (size_t)row * DDIM + 2 * lane));
        float e10 = se[(2 * lane) * 513 + i1], e11v = se[(2 * lane + 1) * 513 + i1];
        float e20 = se[(2 * lane) * 513 + i2], e21v = se[(2 * lane + 1) * 513 + i2];
        float a0 = xv.x - e10, a1 = xv.y - e11v;
        float p1 = fmaf(a0, a0, a1 * a1);
        float b0 = xv.x - e20, b1 = xv.y - e21v;
        float p2 = fmaf(b0, b0, b1 * b1);
#pragma unroll
        for (int o = 16; o > 0; o >>= 1) {
            p1 += __shfl_xor_sync(0xffffffffu, p1, o);
            p2 += __shfl_xor_sync(0xffffffffu, p2, o);
        }
        int bidx = i1; float be = p1;
        float q0 = e10, q1 = e11v;
        if (p2 < be || (p2 == be && i2 < bidx)) { be = p2; bidx = i2; q0 = e20; q1 = e21v; }
        *(float2*)(out_q + (size_t)row * DDIM + 2 * lane) = make_float2(q0, q1);
        if (lane == 0) {
            out_idx[row] = (float)bidx;
            atomicAdd(&g_cluster[bidx], 1.f);
            scatter_row(bidx, row, x);
            loss_acc += be;
        }
    }

    const int qn2 = g_qn2;
    for (int qi = blockIdx.x; qi < qn2; qi += gridDim.x) {
        const int row = g_que2[qi];
        if (tid < 32) {
            float2 v = ((const float2*)(x + (size_t)row * DDIM))[tid];
            xrow[2 * tid] = v.x;
            xrow[2 * tid + 1] = v.y;
        }
        if (tid == 0) *b64 = 0xFFFFFFFFFFFFFFFFull;
        __syncthreads();
        float a = 0.f;
#pragma unroll 8
        for (int d = 0; d < 64; d++) {
            float t = xrow[d] - se[d * 513 + tid];
            a = fmaf(t, t, a);
        }
        unsigned long long loc =
            (((unsigned long long)__float_as_uint(a)) << 32) | (unsigned)tid;
#pragma unroll
        for (int o = 16; o > 0; o >>= 1) {
            unsigned long long ov = __shfl_xor_sync(0xffffffffu, loc, o);
            loc = min(loc, ov);
        }
        if (lane == 0) atomicMin(b64, loc);
        __syncthreads();
        const unsigned long long win = *b64;
        const int bidx = (int)(win & 511u);
        if (tid < 64)
            out_q[(size_t)row * DDIM + tid] = se[tid * 513 + bidx];
        if (tid == 0) {
            out_idx[row] = (float)bidx;
            atomicAdd(&g_cluster[bidx], 1.f);
            scatter_row(bidx, row, x);
            loss_acc += __uint_as_float((uint32_t)(win >> 32));
        }
        __syncthreads();
    }

#pragma unroll
    for (int o = 16; o > 0; o >>= 1)
        loss_acc += __shfl_xor_sync(0xffffffffu, loss_acc, o);
    if (lane == 0 && loss_acc != 0.f) atomicAdd(&g_loss, loss_acc);
}

// ---------------------------------------------------------------------------
// dwsum: block per code; atomic-free register reduction of bucketed rows
// ---------------------------------------------------------------------------
__global__ __launch_bounds__(512)
void k_dwsum(const float* __restrict__ x) {
    __shared__ float red[8][64];
    const int k = blockIdx.x;
    const int tid = threadIdx.x;
    const int d = tid & 63;
    const int grp = tid >> 6;            // 0..7
    const int n = min((int)g_cluster[k], CAP);
    const int* pm = g_perm + k * CAP;

    float acc = 0.f;
    for (int i = grp; i < n; i += 8) {
        int r = __ldg(&pm[i]);
        acc += __ldg(&x[(size_t)r * DDIM + d]);
    }
    red[grp][d] = acc;
    __syncthreads();
    if (tid < 64) {
        float s = red[0][tid];
#pragma unroll
        for (int p = 1; p < 8; p++) s += red[p][tid];
        g_dw[tid * KCB + k] += s;        // overflow fallback already in g_dw
    }
}

// ---------------------------------------------------------------------------
__global__ void k_final(const float* __restrict__ ehc,
                        const float* __restrict__ ehd,
                        const int* __restrict__ counter,
                        float* __restrict__ out) {
    __shared__ float red_n[512];
    __shared__ float red_p[512];

    const int k = threadIdx.x;
    const int d = blockIdx.x;
    const float one_minus_decay = 0.01f;

    float cn = g_cluster[k];
    float t = (float)(*counter + 1);
    float debias = 1.0f - powf(0.99f, t);
    float inv_debias = 1.0f / debias;

    float h    = ehc[k];
    float nhc  = h - (h - cn) * one_minus_decay;
    float avgc = nhc * inv_debias;

    red_n[k] = avgc;
    float p = cn * (1.0f / (float)NROWS);
    red_p[k] = (d == 0) ? p * logf(p + 1e-10f) : 0.f;
    __syncthreads();
#pragma unroll
    for (int s = 256; s > 0; s >>= 1) {
        if (k < s) { red_n[k] += red_n[k + s]; red_p[k] += red_p[k + s]; }
        __syncthreads();
    }
    float n_total = red_n[0];
    float smoothed = (avgc + 1e-5f) / (n_total + (float)KCB * 1e-5f) * n_total;

    float dw  = g_dw[d * KCB + k];
    float hd  = ehd[d * KCB + k];
    float nhd = hd - (hd - dw) * one_minus_decay;
    out[OFF_EMB + d * KCB + k] = (nhd * inv_debias) / smoothed;

    if (d == 0 && k == 0) {
        out[OFF_LOSS] = 0.25f * g_loss / (float)((size_t)NROWS * DDIM);
        out[OFF_PERP] = expf(-red_p[0]);
    }
}

// ---------------------------------------------------------------------------
extern "C" void kernel_launch(void* const* d_in, const int* in_sizes, int n_in,
                              void* d_out, int out_size) {
    const float* x       = (const float*)d_in[0];
    const float* emb     = (const float*)d_in[1];
    const float* ehc     = (const float*)d_in[2];
    const float* ehd     = (const float*)d_in[3];
    const int*   counter = (const int*)d_in[4];
    float* out = (float*)d_out;

    cudaFuncSetAttribute(k_main, cudaFuncAttributeMaxDynamicSharedMemorySize,
                         (int)SMEM_SZ);
    cudaFuncSetAttribute(k_fix, cudaFuncAttributeMaxDynamicSharedMemorySize,
                         (int)FX_SZ);

    k_prep<<<64, 512>>>(emb);
    k_main<<<GRID_MAIN, THREADS, SMEM_SZ>>>(x, emb, out + OFF_Q, out + OFF_IDX);
    k_fix<<<GRID_MAIN, 512, FX_SZ>>>(x, emb, out + OFF_Q, out + OFF_IDX);
    k_dwsum<<<KCB, 512>>>(x);
    k_final<<<64, 512>>>(ehc, ehd, counter, out);
}

// round 16
// speedup vs baseline: 1.0690x; 1.0690x over previous
#include <cuda_runtime.h>
#include <cuda_fp16.h>
#include <cstdint>
#include <math.h>

#define NROWS 131072
#define DDIM  64
#define KCB   512
#define TILE_M 128
#define NTILES (NROWS / TILE_M)     // 1024
#define GRID_MAIN 148
#define THREADS 512
#define CAP 2048                    // per-code bucket capacity (mean 256)

#define OFF_Q    0
#define OFF_LOSS (NROWS * DDIM)
#define OFF_PERP (OFF_LOSS + 1)
#define OFF_EMB  (OFF_PERP + 1)
#define OFF_IDX  (OFF_EMB + DDIM * KCB)

#define MARGIN 0.15625f
#define MASKH  0xFFFFFE00u
#define KEYBIAS 256.0f
#define SENT 0x7F7FFFFFu

__device__ float g_dw[DDIM * KCB];
__device__ float g_cluster[KCB];
__device__ float g_loss;
__device__ float g_enorm[KCB];
__device__ __align__(16) float g_ecbT[KCB * DDIM];   // codebook transposed [k][d]
__device__ int   g_cnt[KCB];        // per-code scatter counters
__device__ int   g_perm[KCB * CAP]; // per-code row buckets
__device__ uint2 g_que[NROWS];
__device__ int   g_que2[NROWS];
__device__ int   g_qn, g_qn2;

__device__ __forceinline__ uint32_t pb(uint32_t d) {
    return ((d >> 1) & 3u) * 32u + (d >> 4) * 8u + ((d >> 3) & 1u) * 4u + (d & 1u) * 2u;
}

// smem layout (bytes) for k_main
#define SO_EH    0u          // 65536
#define SO_XH    65536u      // 16384
#define SO_EN2   81920u      // 2048
#define SO_XN    83968u      // 1024 (2x512 double-buffered)
#define SO_TOP   84992u      // 8192 (2x4096 double-buffered)
#define SO_HIST  93184u      // 2048
#define SMEM_SZ  95232u

__device__ __forceinline__ void mma_f16(float* d, uint32_t a0, uint32_t a1,
                                        uint32_t a2, uint32_t a3,
                                        uint32_t b0, uint32_t b1) {
    asm volatile(
        "mma.sync.aligned.m16n8k16.row.col.f32.f16.f16.f32 "
        "{%0,%1,%2,%3}, {%4,%5,%6,%7}, {%8,%9}, {%0,%1,%2,%3};\n"
        : "+f"(d[0]), "+f"(d[1]), "+f"(d[2]), "+f"(d[3])
        : "r"(a0), "r"(a1), "r"(a2), "r"(a3), "r"(b0), "r"(b1));
}

__device__ __forceinline__ void ins3(uint32_t& m1, uint32_t& m2, uint32_t& m3,
                                     uint32_t k) {
    uint32_t h1 = max(m1, k); m1 = min(m1, k);
    uint32_t h2 = max(m2, h1); m2 = min(m2, h1);
    m3 = min(m3, h2);
}
__device__ __forceinline__ uint32_t mkkey(float dist, uint32_t n) {
    uint32_t r;
    asm("bfi.b32 %0, %1, %2, 0, 9;" : "=r"(r) : "r"(n), "r"(__float_as_uint(dist)));
    return r;
}

// scatter a row into its code bucket; overflow falls back to direct atomics
__device__ __forceinline__ void scatter_row(int bidx, int row,
                                            const float* __restrict__ x) {
    int pos = atomicAdd(&g_cnt[bidx], 1);
    if (pos < CAP) {
        g_perm[bidx * CAP + pos] = row;
    } else {
        const float* xr = x + (size_t)row * DDIM;
        for (int d = 0; d < DDIM; d++)
            atomicAdd(&g_dw[d * KCB + bidx], xr[d]);
    }
}

__device__ __forceinline__ void do_kb(
    const char* sm, int kb, int g, int q,
    const uint4& A0a, const uint4& A0b, const uint4& A1a, const uint4& A1b,
    const float* s_en2, uint32_t c0, uint32_t c1,
    uint32_t& m11, uint32_t& m12, uint32_t& m13,
    uint32_t& m21, uint32_t& m22, uint32_t& m23)
{
    float acc[8][4];
#pragma unroll
    for (int nt = 0; nt < 8; nt++)
#pragma unroll
        for (int j = 0; j < 4; j++) acc[nt][j] = 0.f;

#pragma unroll
    for (int nt = 0; nt < 8; nt++) {
        uint32_t rowb = (uint32_t)(kb * 64 + nt * 8 + g) * 128u;
        uint4 B0 = *(const uint4*)(sm + SO_EH + rowb + c0);
        uint4 B1 = *(const uint4*)(sm + SO_EH + rowb + c1);
        mma_f16(acc[nt], A0a.x, A1a.x, A0a.y, A1a.y, B0.x, B0.y);
        mma_f16(acc[nt], A0a.z, A1a.z, A0a.w, A1a.w, B0.z, B0.w);
        mma_f16(acc[nt], A0b.x, A1b.x, A0b.y, A1b.y, B1.x, B1.y);
        mma_f16(acc[nt], A0b.z, A1b.z, A0b.w, A1b.w, B1.z, B1.w);
    }
#pragma unroll
    for (int nt = 0; nt < 8; nt++) {
        uint32_t n0 = (uint32_t)(kb * 64 + nt * 8 + q * 2);
        float2 en = *(const float2*)&s_en2[n0];
        uint32_t k0 = mkkey(fmaf(-2.f, acc[nt][0], en.x), n0);
        uint32_t k1 = mkkey(fmaf(-2.f, acc[nt][1], en.y), n0 + 1);
        uint32_t k2 = mkkey(fmaf(-2.f, acc[nt][2], en.x), n0);
        uint32_t k3 = mkkey(fmaf(-2.f, acc[nt][3], en.y), n0 + 1);
        ins3(m11, m12, m13, k0);
        ins3(m11, m12, m13, k1);
        ins3(m21, m22, m23, k2);
        ins3(m21, m22, m23, k3);
    }
}

// ---------------------------------------------------------------------------
// Prep (grid 64 x 512): enorm, transposed codebook, zero dw/cnt, reset queues
// ---------------------------------------------------------------------------
__global__ void k_prep(const float* __restrict__ emb) {
    __shared__ float red[8][64];
    const int t = threadIdx.x, b = blockIdx.x;

    g_dw[b * 512 + t] = 0.f;
    {
        int k = b * 8 + (t >> 6), d = t & 63;
        g_ecbT[k * 64 + d] = emb[d * KCB + k];
    }
    if (b < 8) {
        const int kk = t & 63, part = t >> 6;
        const int k = b * 64 + kk;
        float s = 0.f;
#pragma unroll
        for (int j = 0; j < 8; j++) {
            float e = emb[(part * 8 + j) * KCB + k];
            s = fmaf(e, e, s);
        }
        red[part][kk] = s;
        __syncthreads();
        if (t < 64) {
            float tot = red[0][t];
#pragma unroll
            for (int p = 1; p < 8; p++) tot += red[p][t];
            g_enorm[b * 64 + t] = tot;
        }
    }
    if (b == 62) g_cnt[t] = 0;
    if (b == 63) {
        g_cluster[t] = 0.f;
        if (t == 0) { g_loss = 0.f; g_qn = 0; g_qn2 = 0; }
    }
}

// ---------------------------------------------------------------------------
// Main: 512 threads; K-split halves; 2 barriers/tile; scatter on emit
// ---------------------------------------------------------------------------
__global__ __launch_bounds__(THREADS, 1)
void k_main(const float* __restrict__ x, const float* __restrict__ emb,
            float* __restrict__ out_q, float* __restrict__ out_idx) {
    extern __shared__ __align__(1024) char sm[];
    const int tid  = threadIdx.x;
    const int wid  = tid >> 5;
    const int lane = tid & 31;
    const int g    = lane >> 2;
    const int q    = lane & 3;
    const int half = wid >> 3;
    const int w8   = wid & 7;

    float* s_en2  = (float*)(sm + SO_EN2);
    float* s_xn   = (float*)(sm + SO_XN);
    uint4* s_top  = (uint4*)(sm + SO_TOP);
    int*   s_hist = (int*)(sm + SO_HIST);

    for (int i = tid; i < DDIM * KCB; i += THREADS) {
        uint32_t d = (uint32_t)i >> 9, k = (uint32_t)i & 511u;
        uint32_t off = k * 128u + (pb(d) ^ ((k & 7u) * 16u));
        *(__half*)(sm + SO_EH + off) = __float2half_rn(emb[i]);
    }
    s_en2[tid] = g_enorm[tid] + KEYBIAS;
    s_hist[tid] = 0;
    __syncthreads();

    const int r0 = w8 * 16 + g;
    const int r1 = r0 + 8;
    const uint32_t c0 = ((uint32_t)q * 32u) ^ ((uint32_t)g * 16u);
    const uint32_t c1 = ((uint32_t)q * 32u + 16u) ^ ((uint32_t)g * 16u);

    float loss_acc = 0.f;
    int buf = 0;

    for (int tile = blockIdx.x; tile < NTILES; tile += gridDim.x) {
        const float* xt = x + (size_t)tile * TILE_M * DDIM;

#pragma unroll
        for (int it = 0; it < 4; it++) {
            int i = it * THREADS + tid;
            float4 v = ((const float4*)xt)[i];
            uint32_t r = (uint32_t)i >> 4, c = ((uint32_t)i & 15u) * 4u;
            uint32_t xw = (r & 7u) * 16u;
            *(__half2*)(sm + SO_XH + r * 128u + (pb(c) ^ xw)) =
                __floats2half2_rn(v.x, v.y);
            *(__half2*)(sm + SO_XH + r * 128u + (pb(c + 2) ^ xw)) =
                __floats2half2_rn(v.z, v.w);
            float pn = fmaf(v.x, v.x, fmaf(v.y, v.y, fmaf(v.z, v.z, v.w * v.w)));
            pn += __shfl_xor_sync(0xffffffffu, pn, 1);
            pn += __shfl_xor_sync(0xffffffffu, pn, 2);
            pn += __shfl_xor_sync(0xffffffffu, pn, 4);
            pn += __shfl_xor_sync(0xffffffffu, pn, 8);
            if ((tid & 15) == 0) s_xn[buf * 128 + r] = pn;
        }
        __syncthreads();   // barrier 1

        uint4 A0a = *(const uint4*)(sm + SO_XH + (uint32_t)r0 * 128u + c0);
        uint4 A0b = *(const uint4*)(sm + SO_XH + (uint32_t)r0 * 128u + c1);
        uint4 A1a = *(const uint4*)(sm + SO_XH + (uint32_t)r1 * 128u + c0);
        uint4 A1b = *(const uint4*)(sm + SO_XH + (uint32_t)r1 * 128u + c1);

        uint32_t e11 = SENT, e12 = SENT, e13 = SENT;
        uint32_t o11 = SENT, o12 = SENT, o13 = SENT;
        uint32_t e21 = SENT, e22 = SENT, e23 = SENT;
        uint32_t o21 = SENT, o22 = SENT, o23 = SENT;

#pragma unroll 1
        for (int kbp = 0; kbp < 2; kbp++) {
            do_kb(sm, half * 4 + 2 * kbp,     g, q, A0a, A0b, A1a, A1b,
                  s_en2, c0, c1, e11, e12, e13, e21, e22, e23);
            do_kb(sm, half * 4 + 2 * kbp + 1, g, q, A0a, A0b, A1a, A1b,
                  s_en2, c0, c1, o11, o12, o13, o21, o22, o23);
        }
        ins3(e11, e12, e13, o11); ins3(e11, e12, e13, o12); ins3(e11, e12, e13, o13);
        ins3(e21, e22, e23, o21); ins3(e21, e22, e23, o22); ins3(e21, e22, e23, o23);

#pragma unroll
        for (int o = 1; o <= 2; o <<= 1) {
            uint32_t q1 = __shfl_xor_sync(0xffffffffu, e11, o);
            uint32_t q2 = __shfl_xor_sync(0xffffffffu, e12, o);
            uint32_t q3 = __shfl_xor_sync(0xffffffffu, e13, o);
            ins3(e11, e12, e13, q1);
            ins3(e11, e12, e13, q2);
            ins3(e11, e12, e13, q3);
            q1 = __shfl_xor_sync(0xffffffffu, e21, o);
            q2 = __shfl_xor_sync(0xffffffffu, e22, o);
            q3 = __shfl_xor_sync(0xffffffffu, e23, o);
            ins3(e21, e22, e23, q1);
            ins3(e21, e22, e23, q2);
            ins3(e21, e22, e23, q3);
        }
        if (q == 0) {
            s_top[buf * 256 + ((r0 << 1) | half)] = make_uint4(e11, e12, e13, 0u);
            s_top[buf * 256 + ((r1 << 1) | half)] = make_uint4(e21, e22, e23, 0u);
        }
        __syncthreads();   // barrier 2

        // ---- Phase A ----
        {
            const int rloc = tid >> 2;
            const int q4   = tid & 3;
            const int row  = tile * TILE_M + rloc;
            uint4 Ka = s_top[buf * 256 + (rloc << 1)];
            uint4 Kb = s_top[buf * 256 + ((rloc << 1) | 1)];
            uint32_t m1 = Ka.x, m2 = Ka.y, m3 = Ka.z;
            ins3(m1, m2, m3, Kb.x);
            ins3(m1, m2, m3, Kb.y);
            ins3(m1, m2, m3, Kb.z);
            float d1 = __uint_as_float(m1 & MASKH);
            float d2 = __uint_as_float(m2 & MASKH);
            float d3 = __uint_as_float(m3 & MASKH);
            int bidx = (int)(m1 & 511u);
            if (d2 - d1 >= MARGIN) {
                if (q4 == 0) {
                    out_idx[row] = (float)bidx;
                    atomicAdd(&s_hist[bidx], 1);
                    scatter_row(bidx, row, x);
                    loss_acc += d1 - KEYBIAS + s_xn[buf * 128 + rloc]
                              + __uint_as_float(m1 & 0xFF800000u) * 3.0517578125e-05f;
                }
                const float4* ec = (const float4*)(g_ecbT + bidx * DDIM) + q4 * 4;
                float4* oq = (float4*)(out_q + (size_t)row * DDIM) + q4 * 4;
#pragma unroll
                for (int j = 0; j < 4; j++) oq[j] = __ldg(ec + j);
            } else if (q4 == 0) {
                if (d3 - d1 >= MARGIN) {
                    int p = atomicAdd(&g_qn, 1);
                    g_que[p] = make_uint2((unsigned)row,
                                          (m1 & 511u) | ((m2 & 511u) << 16));
                } else {
                    int p = atomicAdd(&g_qn2, 1);
                    g_que2[p] = row;
                }
            }
        }
        buf ^= 1;
    }

#pragma unroll
    for (int o = 16; o > 0; o >>= 1)
        loss_acc += __shfl_xor_sync(0xffffffffu, loss_acc, o);
    if (lane == 0) atomicAdd(&g_loss, loss_acc);

    __syncthreads();
    {
        int c = s_hist[tid];
        if (c) atomicAdd(&g_cluster[tid], (float)c);
    }
}

// ---------------------------------------------------------------------------
// Fix: exact fp32 resolution of queued rows (+ scatter)
// ---------------------------------------------------------------------------
#define FX_XROW (64 * 513)
#define FX_B64  (64 * 513 + 64)
#define FX_SZ   ((64 * 513 + 66) * 4)

__global__ __launch_bounds__(512)
void k_fix(const float* __restrict__ x, const float* __restrict__ emb,
           float* __restrict__ out_q, float* __restrict__ out_idx) {
    extern __shared__ float se[];
    const int tid = threadIdx.x;
    const int wid = tid >> 5;
    const int lane = tid & 31;
    float* xrow = se + FX_XROW;
    unsigned long long* b64 = (unsigned long long*)(se + FX_B64);

    for (int i = tid; i < 64 * 512; i += 512) {
        int d = i >> 9, k = i & 511;
        se[d * 513 + k] = emb[i];
    }
    __syncthreads();

    float loss_acc = 0.f;

    const int qn = g_qn;
    for (int j = blockIdx.x * 16 + wid; j < qn; j += gridDim.x * 16) {
        uint2 e = g_que[j];
        const int row = (int)e.x;
        const int i1 = (int)(e.y & 511u), i2 = (int)((e.y >> 16) & 511u);
        float2 xv = __ldg((const float2*)(x + (size_t)row * DDIM + 2 * lane));
        float e10 = se[(2 * lane) * 513 + i1], e11v = se[(2 * lane + 1) * 513 + i1];
        float e20 = se[(2 * lane) * 513 + i2], e21v = se[(2 * lane + 1) * 513 + i2];
        float a0 = xv.x - e10, a1 = xv.y - e11v;
        float p1 = fmaf(a0, a0, a1 * a1);
        float b0 = xv.x - e20, b1 = xv.y - e21v;
        float p2 = fmaf(b0, b0, b1 * b1);
#pragma unroll
        for (int o = 16; o > 0; o >>= 1) {
            p1 += __shfl_xor_sync(0xffffffffu, p1, o);
            p2 += __shfl_xor_sync(0xffffffffu, p2, o);
        }
        int bidx = i1; float be = p1;
        float q0 = e10, q1 = e11v;
        if (p2 < be || (p2 == be && i2 < bidx)) { be = p2; bidx = i2; q0 = e20; q1 = e21v; }
        *(float2*)(out_q + (size_t)row * DDIM + 2 * lane) = make_float2(q0, q1);
        if (lane == 0) {
            out_idx[row] = (float)bidx;
            atomicAdd(&g_cluster[bidx], 1.f);
            scatter_row(bidx, row, x);
            loss_acc += be;
        }
    }

    const int qn2 = g_qn2;
    for (int qi = blockIdx.x; qi < qn2; qi += gridDim.x) {
        const int row = g_que2[qi];
        if (tid < 32) {
            float2 v = ((const float2*)(x + (size_t)row * DDIM))[tid];
            xrow[2 * tid] = v.x;
            xrow[2 * tid + 1] = v.y;
        }
        if (tid == 0) *b64 = 0xFFFFFFFFFFFFFFFFull;
        __syncthreads();
        float a = 0.f;
#pragma unroll 8
        for (int d = 0; d < 64; d++) {
            float t = xrow[d] - se[d * 513 + tid];
            a = fmaf(t, t, a);
        }
        unsigned long long loc =
            (((unsigned long long)__float_as_uint(a)) << 32) | (unsigned)tid;
#pragma unroll
        for (int o = 16; o > 0; o >>= 1) {
            unsigned long long ov = __shfl_xor_sync(0xffffffffu, loc, o);
            loc = min(loc, ov);
        }
        if (lane == 0) atomicMin(b64, loc);
        __syncthreads();
        const unsigned long long win = *b64;
        const int bidx = (int)(win & 511u);
        if (tid < 64)
            out_q[(size_t)row * DDIM + tid] = se[tid * 513 + bidx];
        if (tid == 0) {
            out_idx[row] = (float)bidx;
            atomicAdd(&g_cluster[bidx], 1.f);
            scatter_row(bidx, row, x);
            loss_acc += __uint_as_float((uint32_t)(win >> 32));
        }
        __syncthreads();
    }

#pragma unroll
    for (int o = 16; o > 0; o >>= 1)
        loss_acc += __shfl_xor_sync(0xffffffffu, loss_acc, o);
    if (lane == 0 && loss_acc != 0.f) atomicAdd(&g_loss, loss_acc);
}

// ---------------------------------------------------------------------------
// dwsum: block per code. Indices staged in smem; x-gather with MLP=4.
// ---------------------------------------------------------------------------
__global__ __launch_bounds__(512)
void k_dwsum(const float* __restrict__ x) {
    __shared__ int spm[CAP];
    __shared__ float red[8][64];
    const int k = blockIdx.x;
    const int tid = threadIdx.x;
    const int n = min(g_cnt[k], CAP);

    for (int i = tid; i < n; i += 512) spm[i] = g_perm[k * CAP + i];
    __syncthreads();

    const int d = tid & 63;
    const int grp = tid >> 6;            // 0..7
    float a0 = 0.f, a1 = 0.f, a2 = 0.f, a3 = 0.f;
    int i = grp;
    for (; i + 24 < n; i += 32) {        // 4 independent loads in flight
        int r0 = spm[i], r1 = spm[i + 8], r2 = spm[i + 16], r3 = spm[i + 24];
        a0 += __ldg(&x[(size_t)r0 * DDIM + d]);
        a1 += __ldg(&x[(size_t)r1 * DDIM + d]);
        a2 += __ldg(&x[(size_t)r2 * DDIM + d]);
        a3 += __ldg(&x[(size_t)r3 * DDIM + d]);
    }
    for (; i < n; i += 8)
        a0 += __ldg(&x[(size_t)spm[i] * DDIM + d]);

    red[grp][d] = (a0 + a2) + (a1 + a3);
    __syncthreads();
    if (tid < 64) {
        float s = red[0][tid];
#pragma unroll
        for (int p = 1; p < 8; p++) s += red[p][tid];
        g_dw[tid * KCB + k] += s;        // overflow fallback already in g_dw
    }
}

// ---------------------------------------------------------------------------
__global__ void k_final(const float* __restrict__ ehc,
                        const float* __restrict__ ehd,
                        const int* __restrict__ counter,
                        float* __restrict__ out) {
    __shared__ float red_n[512];
    __shared__ float red_p[512];

    const int k = threadIdx.x;
    const int d = blockIdx.x;
    const float one_minus_decay = 0.01f;

    float cn = g_cluster[k];
    float t = (float)(*counter + 1);
    float debias = 1.0f - powf(0.99f, t);
    float inv_debias = 1.0f / debias;

    float h    = ehc[k];
    float nhc  = h - (h - cn) * one_minus_decay;
    float avgc = nhc * inv_debias;

    red_n[k] = avgc;
    float p = cn * (1.0f / (float)NROWS);
    red_p[k] = (d == 0) ? p * logf(p + 1e-10f) : 0.f;
    __syncthreads();
#pragma unroll
    for (int s = 256; s > 0; s >>= 1) {
        if (k < s) { red_n[k] += red_n[k + s]; red_p[k] += red_p[k + s]; }
        __syncthreads();
    }
    float n_total = red_n[0];
    float smoothed = (avgc + 1e-5f) / (n_total + (float)KCB * 1e-5f) * n_total;

    float dw  = g_dw[d * KCB + k];
    float hd  = ehd[d * KCB + k];
    float nhd = hd - (hd - dw) * one_minus_decay;
    out[OFF_EMB + d * KCB + k] = (nhd * inv_debias) / smoothed;

    if (d == 0 && k == 0) {
        out[OFF_LOSS] = 0.25f * g_loss / (float)((size_t)NROWS * DDIM);
        out[OFF_PERP] = expf(-red_p[0]);
    }
}

// ---------------------------------------------------------------------------
extern "C" void kernel_launch(void* const* d_in, const int* in_sizes, int n_in,
                              void* d_out, int out_size) {
    const float* x       = (const float*)d_in[0];
    const float* emb     = (const float*)d_in[1];
    const float* ehc     = (const float*)d_in[2];
    const float* ehd     = (const float*)d_in[3];
    const int*   counter = (const int*)d_in[4];
    float* out = (float*)d_out;

    cudaFuncSetAttribute(k_main, cudaFuncAttributeMaxDynamicSharedMemorySize,
                         (int)SMEM_SZ);
    cudaFuncSetAttribute(k_fix, cudaFuncAttributeMaxDynamicSharedMemorySize,
                         (int)FX_SZ);

    k_prep<<<64, 512>>>(emb);
    k_main<<<GRID_MAIN, THREADS, SMEM_SZ>>>(x, emb, out + OFF_Q, out + OFF_IDX);
    k_fix<<<GRID_MAIN, 512, FX_SZ>>>(x, emb, out + OFF_Q, out + OFF_IDX);
    k_dwsum<<<KCB, 512>>>(x);
    k_final<<<64, 512>>>(ehc, ehd, counter, out);
}